// round 1
// baseline (speedup 1.0000x reference)
#include <cuda_runtime.h>
#include <math.h>

// Problem dims (fixed for this instance)
#define BB   128
#define TT   16
#define MTOT (BB * TT)   // 2048
#define H    2048
#define DIN  1024
#define DOUT 1024

// GEMM tiling
#define TM   128
#define TN   128
#define TKK  16
#define NTHR 256

// Scratch (static device memory; allocation in kernel_launch is forbidden)
__device__ float g_X [(size_t)MTOT * H];        // 16 MB  X[(b*16+t), o]
__device__ float g_s0[(size_t)BB * H * TT];     // 16 MB  spikes layer0 [B, H, T]
__device__ float g_s1[(size_t)BB * H * TT];     // 16 MB  spikes layer1 [B, H, T]

// C[(b,t), o] = sum_k A[b, k, t] * W[o, k]
// A: [B, K, T] (t contiguous), W: [N, K] (k contiguous), X: [MTOT, N] row-major
__global__ __launch_bounds__(NTHR, 2)
void gemm_kernel(const float* __restrict__ A,
                 const float* __restrict__ W,
                 float* __restrict__ X,
                 int K, int N)
{
    __shared__ float As[TKK][TM + 4];
    __shared__ float Ws[TKK][TN + 4];

    const int tid = threadIdx.x;
    const int m0  = blockIdx.y * TM;
    const int n0  = blockIdx.x * TN;
    const int tm  = (tid & 15) * 8;   // 16 threads across M
    const int tn  = (tid >> 4) * 8;   // 16 threads across N

    float acc[8][8];
#pragma unroll
    for (int i = 0; i < 8; ++i)
#pragma unroll
        for (int j = 0; j < 8; ++j) acc[i][j] = 0.0f;

    for (int k0 = 0; k0 < K; k0 += TKK) {
        // Stage A tile: elements (k, m), 2048 floats, 8 per thread
#pragma unroll
        for (int r = 0; r < 8; ++r) {
            int idx = tid + r * NTHR;      // 0..2047
            int k   = idx >> 7;            // 0..15
            int m   = idx & 127;
            int gm  = m0 + m;
            int b   = gm >> 4;
            int t   = gm & 15;
            As[k][m] = A[((size_t)b * K + (size_t)(k0 + k)) * TT + t];
        }
        // Stage W tile: elements (k, n), 2048 floats, 8 per thread
#pragma unroll
        for (int r = 0; r < 8; ++r) {
            int idx = tid + r * NTHR;
            int n   = idx >> 4;            // 0..127
            int k   = idx & 15;
            Ws[k][n] = W[(size_t)(n0 + n) * K + (size_t)(k0 + k)];
        }
        __syncthreads();

#pragma unroll
        for (int k = 0; k < TKK; ++k) {
            float a[8], w[8];
#pragma unroll
            for (int i = 0; i < 8; ++i) a[i] = As[k][tm + i];
#pragma unroll
            for (int j = 0; j < 8; ++j) w[j] = Ws[k][tn + j];
#pragma unroll
            for (int i = 0; i < 8; ++i)
#pragma unroll
                for (int j = 0; j < 8; ++j)
                    acc[i][j] = fmaf(a[i], w[j], acc[i][j]);
        }
        __syncthreads();
    }

#pragma unroll
    for (int i = 0; i < 8; ++i) {
        size_t m = (size_t)(m0 + tm + i);
#pragma unroll
        for (int j = 0; j < 8; ++j) {
            X[m * N + (n0 + tn + j)] = acc[i][j];
        }
    }
}

// Fused bias + BN(inference) + LIF over T timesteps.
// X: [MTOT, N]. spk: [B, N, T] (t contiguous). If is_final: out[b,o] = sum_t spikes / 16.
__global__ void lif_kernel(const float* __restrict__ X,
                           const float* __restrict__ bias,
                           const float* __restrict__ gamma,
                           const float* __restrict__ beta,
                           const float* __restrict__ mmean,
                           const float* __restrict__ mvar,
                           float* __restrict__ spk,
                           float* __restrict__ out,
                           int N, int is_final)
{
    int idx = blockIdx.x * blockDim.x + threadIdx.x;
    if (idx >= BB * N) return;
    int o = idx % N;
    int b = idx / N;

    float bo  = bias[o];
    float g   = gamma[o];
    float be  = beta[o];
    float mu  = mmean[o];
    float var = mvar[o];
    float den = sqrtf(__fadd_rn(var, 1e-5f));

    float v = 0.0f, sp = 0.0f;
    float s[TT];
    float cnt = 0.0f;

#pragma unroll
    for (int t = 0; t < TT; ++t) {
        float x  = X[((size_t)b * TT + t) * N + o];
        // Xn = gamma * ((x + bias) - mm) / sqrt(mv + eps) + beta, all separately rounded
        float u  = __fsub_rn(__fadd_rn(x, bo), mu);
        float xn = __fadd_rn(__fdiv_rn(__fmul_rn(g, u), den), be);
        // v = ((v * (1 - sp)) * 0.75) + xn, separately rounded (match non-fused semantics)
        v  = __fadd_rn(__fmul_rn(__fmul_rn(v, __fsub_rn(1.0f, sp)), 0.75f), xn);
        sp = (v > 0.5f) ? 1.0f : 0.0f;
        s[t] = sp;
        cnt += sp;
    }

    if (is_final) {
        out[(size_t)b * N + o] = cnt * 0.0625f;   // exact: cnt is a small integer
    } else {
        float* dst = &spk[((size_t)b * N + o) * TT];
#pragma unroll
        for (int t = 0; t < TT; t += 4) {
            float4 v4 = make_float4(s[t], s[t + 1], s[t + 2], s[t + 3]);
            *reinterpret_cast<float4*>(dst + t) = v4;
        }
    }
}

extern "C" void kernel_launch(void* const* d_in, const int* in_sizes, int n_in,
                              void* d_out, int out_size)
{
    const float* spk_in = (const float*)d_in[0];   // [128, 1024, 16]
    const float* W0  = (const float*)d_in[1];      // [2048, 1024]
    const float* b0  = (const float*)d_in[2];
    const float* g0  = (const float*)d_in[3];
    const float* be0 = (const float*)d_in[4];
    const float* mm0 = (const float*)d_in[5];
    const float* mv0 = (const float*)d_in[6];
    const float* W1  = (const float*)d_in[7];      // [2048, 2048]
    const float* b1  = (const float*)d_in[8];
    const float* g1  = (const float*)d_in[9];
    const float* be1 = (const float*)d_in[10];
    const float* mm1 = (const float*)d_in[11];
    const float* mv1 = (const float*)d_in[12];
    const float* Wo  = (const float*)d_in[13];     // [1024, 2048]
    const float* bo  = (const float*)d_in[14];
    const float* go  = (const float*)d_in[15];
    const float* beo = (const float*)d_in[16];
    const float* mmo = (const float*)d_in[17];
    const float* mvo = (const float*)d_in[18];
    float* out = (float*)d_out;                    // [128, 1024]

    float *X, *s0, *s1;
    cudaGetSymbolAddress((void**)&X,  g_X);
    cudaGetSymbolAddress((void**)&s0, g_s0);
    cudaGetSymbolAddress((void**)&s1, g_s1);

    // Layer 0: K=1024, N=2048
    gemm_kernel<<<dim3(H / TN, MTOT / TM), NTHR>>>(spk_in, W0, X, DIN, H);
    lif_kernel<<<(BB * H + 255) / 256, 256>>>(X, b0, g0, be0, mm0, mv0, s0, nullptr, H, 0);

    // Layer 1: K=2048, N=2048
    gemm_kernel<<<dim3(H / TN, MTOT / TM), NTHR>>>(s0, W1, X, H, H);
    lif_kernel<<<(BB * H + 255) / 256, 256>>>(X, b1, g1, be1, mm1, mv1, s1, nullptr, H, 0);

    // Layer 2: K=2048, N=1024, final (emit averaged spikes)
    gemm_kernel<<<dim3(DOUT / TN, MTOT / TM), NTHR>>>(s1, Wo, X, H, DOUT);
    lif_kernel<<<(BB * DOUT + 255) / 256, 256>>>(X, bo, go, beo, mmo, mvo, nullptr, out, DOUT, 1);
}

// round 4
// speedup vs baseline: 4.7778x; 4.7778x over previous
#include <cuda_runtime.h>
#include <cstdint>
#include <math.h>

#define TT   16
#define MTOT 2048
#define HH   2048
#define DIN  1024
#define DOUT 1024

#define NTHR   512
#define KCB    128        // int8 k-elements (bytes) per chunk = one 128B swizzle row
#define NSTAGE 4

// ---------------- static device scratch ----------------
__device__ __align__(1024) int8_t g_A0 [(size_t)MTOT * DIN];
__device__ __align__(1024) int8_t g_s0 [(size_t)MTOT * HH];
__device__ __align__(1024) int8_t g_s1 [(size_t)MTOT * HH];
__device__ __align__(1024) int8_t g_W0q[(size_t)HH   * 3 * DIN];
__device__ __align__(1024) int8_t g_W1q[(size_t)HH   * 3 * HH];
__device__ __align__(1024) int8_t g_Woq[(size_t)DOUT * 3 * HH];

// ---------------- helpers ----------------
__device__ __forceinline__ uint32_t smem_u32(const void* p) {
    uint32_t a;
    asm("{ .reg .u64 t; cvta.to.shared.u64 t, %1; cvt.u32.u64 %0, t; }" : "=r"(a) : "l"(p));
    return a;
}
__device__ __forceinline__ void cp16(uint32_t dst, const void* src) {
    asm volatile("cp.async.cg.shared.global [%0], [%1], 16;" :: "r"(dst), "l"(src));
}
#define CP_COMMIT() asm volatile("cp.async.commit_group;" ::: "memory")
#define CP_WAIT(n)  asm volatile("cp.async.wait_group %0;" :: "n"(n) : "memory")
#define SWZ(off) ((off) ^ (((off) >> 3) & 0x70))

__device__ __forceinline__ void ldsm4(uint32_t& r0, uint32_t& r1, uint32_t& r2, uint32_t& r3,
                                      uint32_t addr) {
    asm volatile("ldmatrix.sync.aligned.m8n8.x4.shared.b16 {%0,%1,%2,%3}, [%4];"
                 : "=r"(r0), "=r"(r1), "=r"(r2), "=r"(r3) : "r"(addr));
}
__device__ __forceinline__ void imma(int* d, const uint32_t* a, uint32_t b0, uint32_t b1) {
    asm volatile(
        "mma.sync.aligned.m16n8k32.row.col.s32.s8.s8.s32 "
        "{%0,%1,%2,%3}, {%4,%5,%6,%7}, {%8,%9}, {%0,%1,%2,%3};"
        : "+r"(d[0]), "+r"(d[1]), "+r"(d[2]), "+r"(d[3])
        : "r"(a[0]), "r"(a[1]), "r"(a[2]), "r"(a[3]), "r"(b0), "r"(b1));
}

// ---------------- pre-kernels ----------------
// W fp32 [N,K] -> 3 signed int8 limb planes of round(w * 2^27), stored per row:
// Wq[n][0..K) = top limb (l2), [K..2K) = mid (l1), [2K..3K) = low (l0).
// Exact: l2*2^16 + l1*2^8 + l0 == round(w*2^27); |l2| <= 64.
__global__ void quant_w(const float* __restrict__ W, int8_t* __restrict__ Wq,
                        int N, int K) {
    int idx = blockIdx.x * blockDim.x + threadIdx.x;
    if (idx >= N * K) return;
    int n = idx / K, k = idx % K;
    long long wi = llrintf(W[idx] * 134217728.0f);   // 2^27, product exact (pow2 scale)
    int l0 = (int)((wi + 128) & 255) - 128;  wi = (wi - l0) >> 8;
    int l1 = (int)((wi + 128) & 255) - 128;  wi = (wi - l1) >> 8;
    int l2 = (int)wi;
    size_t base = (size_t)n * 3 * K + k;
    Wq[base]         = (int8_t)l2;
    Wq[base + K]     = (int8_t)l1;
    Wq[base + 2 * K] = (int8_t)l0;
}

// input spikes fp32 [B, DIN, T] (0/1) -> int8 A[(b*16+t), DIN]
__global__ void conv_in(const float* __restrict__ in, int8_t* __restrict__ A) {
    int idx = blockIdx.x * blockDim.x + threadIdx.x;
    if (idx >= MTOT * DIN) return;
    int m = idx / DIN, k = idx % DIN;
    int b = m >> 4, t = m & 15;
    A[idx] = (int8_t)(in[((size_t)b * DIN + k) * TT + t] > 0.5f ? 1 : 0);
}

// ---------------- fused exact-GEMM (s8 IMMA) + BN + LIF ----------------
template<bool FINAL>
__global__ __launch_bounds__(NTHR, 1)
void gemm_lif(const int8_t* __restrict__ A,
              const int8_t* __restrict__ Wq,
              const float* __restrict__ bias, const float* __restrict__ gamma,
              const float* __restrict__ beta, const float* __restrict__ mmean,
              const float* __restrict__ mvar,
              int8_t* __restrict__ spk, float* __restrict__ out,
              int K, int N)
{
    const int KP   = 3 * K;
    const int nchP = K / KCB;         // chunks per limb plane
    const int nch  = 3 * nchP;
    constexpr int ABYTES = 128 * KCB; // 16 KB
    constexpr int STAGE  = 2 * ABYTES;

    extern __shared__ __align__(16) char dsm[];
    char* sm = (char*)(((uintptr_t)dsm + 1023) & ~(uintptr_t)1023);
    const uint32_t sm32 = smem_u32(sm);

    const int tid   = threadIdx.x;
    const int wid   = tid >> 5;
    const int lane  = tid & 31;
    const int warpM = wid & 3;        // 4 M-groups of 32
    const int warpN = wid >> 2;       // 4 N-groups of 32
    const int m0    = blockIdx.y * 128;
    const int n0    = blockIdx.x * 128;

    int accH[2][4][4], accL[2][4][4];
#pragma unroll
    for (int i = 0; i < 2; ++i)
#pragma unroll
        for (int j = 0; j < 4; ++j)
#pragma unroll
            for (int q = 0; q < 4; ++q) { accH[i][j][q] = 0; accL[i][j][q] = 0; }

    auto load_chunk = [&](int c) {
        const uint32_t sbase = sm32 + (uint32_t)(c & 3) * STAGE;
        const int8_t* gA = A + (size_t)m0 * K + (c % nchP) * KCB;
#pragma unroll
        for (int u = tid; u < 1024; u += NTHR) {
            int r = u >> 3, q = u & 7;
            cp16(sbase + SWZ((uint32_t)(r * 128 + q * 16)), gA + (size_t)r * K + q * 16);
        }
        const int8_t* gB = Wq + (size_t)n0 * KP + c * KCB;
        const uint32_t bbase = sbase + ABYTES;
#pragma unroll
        for (int u = tid; u < 1024; u += NTHR) {
            int r = u >> 3, q = u & 7;
            cp16(bbase + SWZ((uint32_t)(r * 128 + q * 16)), gB + (size_t)r * KP + q * 16);
        }
    };

    for (int c = 0; c < 3; ++c) { load_chunk(c); CP_COMMIT(); }

    const int aRowB = warpM * 32 + (lane & 7) + ((lane >> 3) & 1) * 8;  // + mf*16
    const int aColB = ((lane >> 4) & 1) * 16;                           // + ks*32
    const int bRowB = warpN * 32 + (lane & 7) + ((lane >> 4) & 1) * 8;  // + bg*16
    const int bColB = ((lane >> 3) & 1) * 16;                           // + ks*32

#define KSWEEP(ACC)                                                                   \
    {                                                                                 \
        _Pragma("unroll")                                                             \
        for (int ks = 0; ks < 4; ++ks) {                                              \
            const int kb = ks * 32;                                                   \
            uint32_t a[2][4], b[2][4];                                                \
            _Pragma("unroll")                                                         \
            for (int mf = 0; mf < 2; ++mf)                                            \
                ldsm4(a[mf][0], a[mf][1], a[mf][2], a[mf][3],                         \
                      sA + SWZ((uint32_t)((aRowB + mf * 16) * 128 + aColB + kb)));    \
            _Pragma("unroll")                                                         \
            for (int bg = 0; bg < 2; ++bg)                                            \
                ldsm4(b[bg][0], b[bg][1], b[bg][2], b[bg][3],                         \
                      sB + SWZ((uint32_t)((bRowB + bg * 16) * 128 + bColB + kb)));    \
            _Pragma("unroll")                                                         \
            for (int mf = 0; mf < 2; ++mf)                                            \
                _Pragma("unroll")                                                     \
                for (int nf = 0; nf < 4; ++nf)                                        \
                    imma(ACC[mf][nf], a[mf],                                          \
                         b[nf >> 1][(nf & 1) * 2], b[nf >> 1][(nf & 1) * 2 + 1]);     \
        }                                                                             \
    }

    for (int i = 0; i < nch; ++i) {
        CP_WAIT(2);
        __syncthreads();

        if (i == 2 * nchP) {           // entering low-limb plane: exact Horner *256
#pragma unroll
            for (int mf = 0; mf < 2; ++mf)
#pragma unroll
                for (int nf = 0; nf < 4; ++nf)
#pragma unroll
                    for (int q = 0; q < 4; ++q) accL[mf][nf][q] <<= 8;
        }

        const uint32_t sA = sm32 + (uint32_t)(i & 3) * STAGE;
        const uint32_t sB = sA + ABYTES;
        if (i < nchP) KSWEEP(accH) else KSWEEP(accL);

        if (i + 3 < nch) load_chunk(i + 3);
        CP_COMMIT();
    }
#undef KSWEEP

    CP_WAIT(0);
    __syncthreads();   // stage buffers now reusable

    // ---- exact recombine: X = (accH*2^16 + accL) * 2^-27, single fp32 rounding ----
    float* scrF = (float*)sm;                         // [128][132]
    const double SH = 4.8828125e-4;                   // 2^-11
    const double SL = 7.450580596923828125e-9;        // 2^-27
    const int r0w = warpM * 32 + (lane >> 2);
    const int c0w = warpN * 32 + (lane & 3) * 2;
#pragma unroll
    for (int mf = 0; mf < 2; ++mf) {
#pragma unroll
        for (int nf = 0; nf < 4; ++nf) {
            int r = r0w + mf * 16;
            int c = c0w + nf * 8;
            float x0 = (float)((double)accH[mf][nf][0] * SH + (double)accL[mf][nf][0] * SL);
            float x1 = (float)((double)accH[mf][nf][1] * SH + (double)accL[mf][nf][1] * SL);
            float x2 = (float)((double)accH[mf][nf][2] * SH + (double)accL[mf][nf][2] * SL);
            float x3 = (float)((double)accH[mf][nf][3] * SH + (double)accL[mf][nf][3] * SL);
            *(float2*)&scrF[r * 132 + c]       = make_float2(x0, x1);
            *(float2*)&scrF[(r + 8) * 132 + c] = make_float2(x2, x3);
        }
    }
    __syncthreads();

    // ---- BN + LIF (round-1 exact elementwise ops) ----
    int8_t* scrS = (int8_t*)(sm + 67584);             // [128][144]
#pragma unroll
    for (int task = tid; task < 1024; task += NTHR) {
        const int col = task & 127;
        const int bb  = task >> 7;
        const int n   = n0 + col;

        const float bo  = bias[n];
        const float ga  = gamma[n];
        const float be  = beta[n];
        const float mu  = mmean[n];
        const float var = mvar[n];
        const float den = sqrtf(__fadd_rn(var, 1e-5f));

        float v = 0.0f, sp = 0.0f, cnt = 0.0f;
#pragma unroll
        for (int t = 0; t < TT; ++t) {
            float x  = scrF[(bb * 16 + t) * 132 + col];
            float u  = __fsub_rn(__fadd_rn(x, bo), mu);
            float xn = __fadd_rn(__fdiv_rn(__fmul_rn(ga, u), den), be);
            v  = __fadd_rn(__fmul_rn(__fmul_rn(v, __fsub_rn(1.0f, sp)), 0.75f), xn);
            sp = (v > 0.5f) ? 1.0f : 0.0f;
            if (FINAL) cnt += sp;
            else       scrS[(bb * 16 + t) * 144 + col] = (int8_t)sp;
        }
        if (FINAL) {
            int bg = (m0 >> 4) + bb;
            out[(size_t)bg * N + n] = cnt * 0.0625f;
        }
    }

    if (!FINAL) {
        __syncthreads();
        // coalesced spike copy-out: 128 rows x 128B
#pragma unroll
        for (int u = tid; u < 1024; u += NTHR) {
            int r = u >> 3, seg = u & 7;
            uint4 val = *(const uint4*)(scrS + r * 144 + seg * 16);
            *(uint4*)(spk + (size_t)(m0 + r) * N + n0 + seg * 16) = val;
        }
    }
}

// ---------------- host ----------------
extern "C" void kernel_launch(void* const* d_in, const int* in_sizes, int n_in,
                              void* d_out, int out_size)
{
    const float* spk_in = (const float*)d_in[0];
    const float* W0  = (const float*)d_in[1];
    const float* b0  = (const float*)d_in[2];
    const float* g0  = (const float*)d_in[3];
    const float* be0 = (const float*)d_in[4];
    const float* mm0 = (const float*)d_in[5];
    const float* mv0 = (const float*)d_in[6];
    const float* W1  = (const float*)d_in[7];
    const float* b1  = (const float*)d_in[8];
    const float* g1  = (const float*)d_in[9];
    const float* be1 = (const float*)d_in[10];
    const float* mm1 = (const float*)d_in[11];
    const float* mv1 = (const float*)d_in[12];
    const float* Wo  = (const float*)d_in[13];
    const float* bo  = (const float*)d_in[14];
    const float* go  = (const float*)d_in[15];
    const float* beo = (const float*)d_in[16];
    const float* mmo = (const float*)d_in[17];
    const float* mvo = (const float*)d_in[18];
    float* out = (float*)d_out;

    int8_t *A0, *s0, *s1, *W0q, *W1q, *Woq;
    cudaGetSymbolAddress((void**)&A0,  g_A0);
    cudaGetSymbolAddress((void**)&s0,  g_s0);
    cudaGetSymbolAddress((void**)&s1,  g_s1);
    cudaGetSymbolAddress((void**)&W0q, g_W0q);
    cudaGetSymbolAddress((void**)&W1q, g_W1q);
    cudaGetSymbolAddress((void**)&Woq, g_Woq);

    const int SMEM = NSTAGE * 2 * 128 * KCB + 1024;   // 132096
    cudaFuncSetAttribute((const void*)gemm_lif<false>,
                         cudaFuncAttributeMaxDynamicSharedMemorySize, SMEM);
    cudaFuncSetAttribute((const void*)gemm_lif<true>,
                         cudaFuncAttributeMaxDynamicSharedMemorySize, SMEM);

    quant_w<<<(HH * DIN + 255) / 256, 256>>>(W0, W0q, HH, DIN);
    quant_w<<<(HH * HH + 255) / 256, 256>>>(W1, W1q, HH, HH);
    quant_w<<<(DOUT * HH + 255) / 256, 256>>>(Wo, Woq, DOUT, HH);
    conv_in<<<(MTOT * DIN + 255) / 256, 256>>>(spk_in, A0);

    // Layer 0: K=1024, N=2048
    gemm_lif<false><<<dim3(HH / 128, MTOT / 128), NTHR, SMEM>>>(
        A0, W0q, b0, g0, be0, mm0, mv0, s0, nullptr, DIN, HH);
    // Layer 1: K=2048, N=2048
    gemm_lif<false><<<dim3(HH / 128, MTOT / 128), NTHR, SMEM>>>(
        s0, W1q, b1, g1, be1, mm1, mv1, s1, nullptr, HH, HH);
    // Layer 2: K=2048, N=1024, final
    gemm_lif<true><<<dim3(DOUT / 128, MTOT / 128), NTHR, SMEM>>>(
        s1, Woq, bo, go, beo, mmo, mvo, nullptr, out, HH, DOUT);
}

// round 5
// speedup vs baseline: 5.0087x; 1.0483x over previous
#include <cuda_runtime.h>
#include <cstdint>
#include <math.h>

#define TT   16
#define MTOT 2048
#define HH   2048
#define DIN  1024
#define DOUT 1024

#define NTHR 512
#define KCB  128          // int8 k per super-chunk (one 128B swizzle row)

// ---------------- static device scratch ----------------
__device__ __align__(1024) int8_t g_A0 [(size_t)MTOT * DIN];
__device__ __align__(1024) int8_t g_s0 [(size_t)MTOT * HH];
__device__ __align__(1024) int8_t g_s1 [(size_t)MTOT * HH];
__device__ __align__(1024) int8_t g_W0q[(size_t)HH   * 3 * DIN];
__device__ __align__(1024) int8_t g_W1q[(size_t)HH   * 3 * HH];
__device__ __align__(1024) int8_t g_Woq[(size_t)DOUT * 3 * HH];

// ---------------- helpers ----------------
__device__ __forceinline__ uint32_t smem_u32(const void* p) {
    uint32_t a;
    asm("{ .reg .u64 t; cvta.to.shared.u64 t, %1; cvt.u32.u64 %0, t; }" : "=r"(a) : "l"(p));
    return a;
}
__device__ __forceinline__ void cp16(uint32_t dst, const void* src) {
    asm volatile("cp.async.cg.shared.global [%0], [%1], 16;" :: "r"(dst), "l"(src));
}
#define CP_COMMIT() asm volatile("cp.async.commit_group;" ::: "memory")
#define CP_WAIT(n)  asm volatile("cp.async.wait_group %0;" :: "n"(n) : "memory")
#define SWZ(off) ((off) ^ (((off) >> 3) & 0x70))

__device__ __forceinline__ void ldsm4(uint32_t& r0, uint32_t& r1, uint32_t& r2, uint32_t& r3,
                                      uint32_t addr) {
    asm volatile("ldmatrix.sync.aligned.m8n8.x4.shared.b16 {%0,%1,%2,%3}, [%4];"
                 : "=r"(r0), "=r"(r1), "=r"(r2), "=r"(r3) : "r"(addr));
}
__device__ __forceinline__ void imma(int* d, const uint32_t* a, uint32_t b0, uint32_t b1) {
    asm volatile(
        "mma.sync.aligned.m16n8k32.row.col.s32.s8.s8.s32 "
        "{%0,%1,%2,%3}, {%4,%5,%6,%7}, {%8,%9}, {%0,%1,%2,%3};"
        : "+r"(d[0]), "+r"(d[1]), "+r"(d[2]), "+r"(d[3])
        : "r"(a[0]), "r"(a[1]), "r"(a[2]), "r"(a[3]), "r"(b0), "r"(b1));
}

// ---------------- pre-kernels ----------------
// W fp32 [N,K] -> 3 signed int8 limb planes of round(w * 2^27):
// row n: [0..K) = l2 (top), [K..2K) = l1, [2K..3K) = l0. l2*2^16 + l1*2^8 + l0 exact.
__global__ void quant_w(const float* __restrict__ W, int8_t* __restrict__ Wq,
                        int N, int K) {
    int i4 = blockIdx.x * blockDim.x + threadIdx.x;
    int total4 = (N * K) >> 2;
    if (i4 >= total4) return;
    int idx = i4 << 2;
    int n = idx / K, k = idx % K;
    float4 w4 = *(const float4*)(W + idx);
    char l2v[4], l1v[4], l0v[4];
    float wv[4] = {w4.x, w4.y, w4.z, w4.w};
#pragma unroll
    for (int j = 0; j < 4; ++j) {
        long long wi = llrintf(wv[j] * 134217728.0f);  // 2^27
        int l0 = (int)((wi + 128) & 255) - 128;  wi = (wi - l0) >> 8;
        int l1 = (int)((wi + 128) & 255) - 128;  wi = (wi - l1) >> 8;
        l2v[j] = (char)wi; l1v[j] = (char)l1; l0v[j] = (char)l0;
    }
    size_t base = (size_t)n * 3 * K + k;
    *(char4*)(Wq + base)         = make_char4(l2v[0], l2v[1], l2v[2], l2v[3]);
    *(char4*)(Wq + base + K)     = make_char4(l1v[0], l1v[1], l1v[2], l1v[3]);
    *(char4*)(Wq + base + 2 * K) = make_char4(l0v[0], l0v[1], l0v[2], l0v[3]);
}

// input spikes fp32 [B, DIN, T] (0/1) -> int8 A[(b*16+t), DIN], smem transpose per b
__global__ __launch_bounds__(256)
void conv_in(const float* __restrict__ in, int8_t* __restrict__ A) {
    __shared__ int8_t s[TT][DIN];
    const int b = blockIdx.x;
    const int tid = threadIdx.x;
    // read: each thread handles 4 k-rows; row = 16 floats = 4 float4, contiguous
#pragma unroll
    for (int r = 0; r < 4; ++r) {
        int k = tid + r * 256;
        const float4* src = (const float4*)(in + ((size_t)b * DIN + k) * TT);
#pragma unroll
        for (int q = 0; q < 4; ++q) {
            float4 v = src[q];
            s[q * 4 + 0][k] = (int8_t)(v.x > 0.5f ? 1 : 0);
            s[q * 4 + 1][k] = (int8_t)(v.y > 0.5f ? 1 : 0);
            s[q * 4 + 2][k] = (int8_t)(v.z > 0.5f ? 1 : 0);
            s[q * 4 + 3][k] = (int8_t)(v.w > 0.5f ? 1 : 0);
        }
    }
    __syncthreads();
    // write: 16 rows x 1024B, uint4 coalesced
#pragma unroll
    for (int u = tid; u < TT * (DIN / 16); u += 256) {
        int t = u >> 6, seg = u & 63;
        *(uint4*)(A + ((size_t)b * TT + t) * DIN + seg * 16) =
            *(const uint4*)(&s[t][seg * 16]);
    }
}

// ---------------- fused exact-GEMM (s8 IMMA, 3 limb planes per chunk) + BN + LIF ----------------
template<bool FINAL>
__global__ __launch_bounds__(NTHR, 1)
void gemm_lif(const int8_t* __restrict__ A,
              const int8_t* __restrict__ Wq,
              const float* __restrict__ bias, const float* __restrict__ gamma,
              const float* __restrict__ beta, const float* __restrict__ mmean,
              const float* __restrict__ mvar,
              int8_t* __restrict__ spk, float* __restrict__ out,
              int K, int N)
{
    const int KP  = 3 * K;
    const int nsc = K / KCB;              // super-chunks
    constexpr int ABYTES = 128 * KCB;     // 16 KB A tile
    constexpr int PBYTES = 128 * KCB;     // 16 KB per B plane
    constexpr int STAGE  = ABYTES + 3 * PBYTES;   // 64 KB

    extern __shared__ __align__(16) char dsm[];
    char* sm = (char*)(((uintptr_t)dsm + 1023) & ~(uintptr_t)1023);
    const uint32_t sm32 = smem_u32(sm);

    const int tid   = threadIdx.x;
    const int wid   = tid >> 5;
    const int lane  = tid & 31;
    const int warpM = wid & 3;            // 4 M-groups of 32
    const int warpN = wid >> 2;           // 4 N-groups of 32
    const int m0    = blockIdx.y * 128;
    const int n0    = blockIdx.x * 128;

    int acc[3][2][4][4];                  // [plane][mf][nf][quad]
#pragma unroll
    for (int p = 0; p < 3; ++p)
#pragma unroll
        for (int i = 0; i < 2; ++i)
#pragma unroll
            for (int j = 0; j < 4; ++j)
#pragma unroll
                for (int q = 0; q < 4; ++q) acc[p][i][j][q] = 0;

    auto load_chunk = [&](int c) {
        const uint32_t sbase = sm32 + (uint32_t)(c % 3) * STAGE;
        const int8_t* gA = A + (size_t)m0 * K + c * KCB;
#pragma unroll
        for (int u = tid; u < 1024; u += NTHR) {
            int r = u >> 3, q = u & 7;
            cp16(sbase + SWZ((uint32_t)(r * 128 + q * 16)), gA + (size_t)r * K + q * 16);
        }
#pragma unroll
        for (int p = 0; p < 3; ++p) {
            const int8_t* gB = Wq + (size_t)n0 * KP + p * K + c * KCB;
            const uint32_t bbase = sbase + ABYTES + (uint32_t)p * PBYTES;
#pragma unroll
            for (int u = tid; u < 1024; u += NTHR) {
                int r = u >> 3, q = u & 7;
                cp16(bbase + SWZ((uint32_t)(r * 128 + q * 16)), gB + (size_t)r * KP + q * 16);
            }
        }
    };

    load_chunk(0); CP_COMMIT();
    if (nsc > 1) { load_chunk(1); CP_COMMIT(); }
    else         { CP_COMMIT(); }         // keep group count uniform

    const int aRowB = warpM * 32 + (lane & 7) + ((lane >> 3) & 1) * 8;  // + mf*16
    const int aColB = ((lane >> 4) & 1) * 16;                           // + ks*32
    const int bRowB = warpN * 32 + (lane & 7) + ((lane >> 4) & 1) * 8;  // + bg*16
    const int bColB = ((lane >> 3) & 1) * 16;                           // + ks*32

    for (int i = 0; i < nsc; ++i) {
        CP_WAIT(1);
        __syncthreads();

        if (i + 2 < nsc) load_chunk(i + 2);
        CP_COMMIT();

        const uint32_t sA = sm32 + (uint32_t)(i % 3) * STAGE;
        const uint32_t sB = sA + ABYTES;

#pragma unroll
        for (int ks = 0; ks < 4; ++ks) {
            const int kb = ks * 32;
            uint32_t a[2][4];
#pragma unroll
            for (int mf = 0; mf < 2; ++mf)
                ldsm4(a[mf][0], a[mf][1], a[mf][2], a[mf][3],
                      sA + SWZ((uint32_t)((aRowB + mf * 16) * 128 + aColB + kb)));
#pragma unroll
            for (int p = 0; p < 3; ++p) {
                uint32_t b[2][4];
#pragma unroll
                for (int bg = 0; bg < 2; ++bg)
                    ldsm4(b[bg][0], b[bg][1], b[bg][2], b[bg][3],
                          sB + (uint32_t)p * PBYTES +
                          SWZ((uint32_t)((bRowB + bg * 16) * 128 + bColB + kb)));
#pragma unroll
                for (int mf = 0; mf < 2; ++mf)
#pragma unroll
                    for (int nf = 0; nf < 4; ++nf)
                        imma(acc[p][mf][nf], a[mf],
                             b[nf >> 1][(nf & 1) * 2], b[nf >> 1][(nf & 1) * 2 + 1]);
            }
        }
    }

    CP_WAIT(0);
    __syncthreads();   // stage buffers now reusable

    // ---- exact recombine: X = (accH*2^16 + accM*2^8 + accL) * 2^-27, single fp32 rounding ----
    float* scrF = (float*)sm;                          // [128][132]
    const double SL = 7.450580596923828125e-9;         // 2^-27
    const int r0w = warpM * 32 + (lane >> 2);
    const int c0w = warpN * 32 + (lane & 3) * 2;
#pragma unroll
    for (int mf = 0; mf < 2; ++mf) {
#pragma unroll
        for (int nf = 0; nf < 4; ++nf) {
            int r = r0w + mf * 16;
            int c = c0w + nf * 8;
            float x[4];
#pragma unroll
            for (int q = 0; q < 4; ++q) {
                double s = (double)acc[0][mf][nf][q] * 65536.0
                         + (double)acc[1][mf][nf][q] * 256.0
                         + (double)acc[2][mf][nf][q];
                x[q] = (float)(s * SL);
            }
            *(float2*)&scrF[r * 132 + c]       = make_float2(x[0], x[1]);
            *(float2*)&scrF[(r + 8) * 132 + c] = make_float2(x[2], x[3]);
        }
    }
    __syncthreads();

    // ---- BN + LIF (exact elementwise ops, bit-identical to reference semantics) ----
    int8_t* scrS = (int8_t*)(sm + 67584);              // [128][144]
#pragma unroll
    for (int task = tid; task < 1024; task += NTHR) {
        const int col = task & 127;
        const int bb  = task >> 7;
        const int n   = n0 + col;

        const float bo  = bias[n];
        const float ga  = gamma[n];
        const float be  = beta[n];
        const float mu  = mmean[n];
        const float var = mvar[n];
        const float den = sqrtf(__fadd_rn(var, 1e-5f));

        float v = 0.0f, sp = 0.0f, cnt = 0.0f;
#pragma unroll
        for (int t = 0; t < TT; ++t) {
            float x  = scrF[(bb * 16 + t) * 132 + col];
            float u  = __fsub_rn(__fadd_rn(x, bo), mu);
            float xn = __fadd_rn(__fdiv_rn(__fmul_rn(ga, u), den), be);
            v  = __fadd_rn(__fmul_rn(__fmul_rn(v, __fsub_rn(1.0f, sp)), 0.75f), xn);
            sp = (v > 0.5f) ? 1.0f : 0.0f;
            if (FINAL) cnt += sp;
            else       scrS[(bb * 16 + t) * 144 + col] = (int8_t)sp;
        }
        if (FINAL) {
            int bg = (m0 >> 4) + bb;
            out[(size_t)bg * N + n] = cnt * 0.0625f;
        }
    }

    if (!FINAL) {
        __syncthreads();
#pragma unroll
        for (int u = tid; u < 1024; u += NTHR) {
            int r = u >> 3, seg = u & 7;
            uint4 val = *(const uint4*)(scrS + r * 144 + seg * 16);
            *(uint4*)(spk + (size_t)(m0 + r) * N + n0 + seg * 16) = val;
        }
    }
}

// ---------------- host ----------------
extern "C" void kernel_launch(void* const* d_in, const int* in_sizes, int n_in,
                              void* d_out, int out_size)
{
    const float* spk_in = (const float*)d_in[0];
    const float* W0  = (const float*)d_in[1];
    const float* b0  = (const float*)d_in[2];
    const float* g0  = (const float*)d_in[3];
    const float* be0 = (const float*)d_in[4];
    const float* mm0 = (const float*)d_in[5];
    const float* mv0 = (const float*)d_in[6];
    const float* W1  = (const float*)d_in[7];
    const float* b1  = (const float*)d_in[8];
    const float* g1  = (const float*)d_in[9];
    const float* be1 = (const float*)d_in[10];
    const float* mm1 = (const float*)d_in[11];
    const float* mv1 = (const float*)d_in[12];
    const float* Wo  = (const float*)d_in[13];
    const float* bo  = (const float*)d_in[14];
    const float* go  = (const float*)d_in[15];
    const float* beo = (const float*)d_in[16];
    const float* mmo = (const float*)d_in[17];
    const float* mvo = (const float*)d_in[18];
    float* out = (float*)d_out;

    int8_t *A0, *s0, *s1, *W0q, *W1q, *Woq;
    cudaGetSymbolAddress((void**)&A0,  g_A0);
    cudaGetSymbolAddress((void**)&s0,  g_s0);
    cudaGetSymbolAddress((void**)&s1,  g_s1);
    cudaGetSymbolAddress((void**)&W0q, g_W0q);
    cudaGetSymbolAddress((void**)&W1q, g_W1q);
    cudaGetSymbolAddress((void**)&Woq, g_Woq);

    const int SMEM = 3 * (4 * 128 * KCB) + 1024;   // 3 stages x 64KB + align = 197632
    cudaFuncSetAttribute((const void*)gemm_lif<false>,
                         cudaFuncAttributeMaxDynamicSharedMemorySize, SMEM);
    cudaFuncSetAttribute((const void*)gemm_lif<true>,
                         cudaFuncAttributeMaxDynamicSharedMemorySize, SMEM);

    quant_w<<<(HH * DIN / 4 + 255) / 256, 256>>>(W0, W0q, HH, DIN);
    quant_w<<<(HH * HH / 4 + 255) / 256, 256>>>(W1, W1q, HH, HH);
    quant_w<<<(DOUT * HH / 4 + 255) / 256, 256>>>(Wo, Woq, DOUT, HH);
    conv_in<<<128, 256>>>(spk_in, A0);

    // Layer 0: K=1024, N=2048
    gemm_lif<false><<<dim3(HH / 128, MTOT / 128), NTHR, SMEM>>>(
        A0, W0q, b0, g0, be0, mm0, mv0, s0, nullptr, DIN, HH);
    // Layer 1: K=2048, N=2048
    gemm_lif<false><<<dim3(HH / 128, MTOT / 128), NTHR, SMEM>>>(
        s0, W1q, b1, g1, be1, mm1, mv1, s1, nullptr, HH, HH);
    // Layer 2: K=2048, N=1024, final
    gemm_lif<true><<<dim3(DOUT / 128, MTOT / 128), NTHR, SMEM>>>(
        s1, Woq, bo, go, beo, mmo, mvo, nullptr, out, HH, DOUT);
}